// round 6
// baseline (speedup 1.0000x reference)
#include <cuda_runtime.h>
#include <cstdint>

namespace {
constexpr int Bn  = 2;
constexpr int Sn  = 2048;
constexpr int Dn  = 1024;
constexpr int Hn  = 16;
constexpr int DKn = 64;
constexpr int Mn  = Bn * Sn;    // 4096
constexpr int BHn = Bn * Hn;    // 32
constexpr int RowsTot = BHn * Sn;  // 65536 attn rows
constexpr int JB = Sn / 128;       // 16 j-blocks per row
}

// Scratch (no cudaMalloc allowed)
__device__ float g_q[(size_t)BHn * Sn * DKn];
__device__ float g_k[(size_t)BHn * Sn * DKn];
__device__ float g_v[(size_t)BHn * Sn * DKn];
__device__ float g_ctx[(size_t)Mn * Dn];
__device__ float g_xout[(size_t)Mn * Dn];
__device__ float g_partial[(size_t)JB * RowsTot];
__device__ float g_inv[RowsTot];

// --------------------------- tf32 mma helpers ------------------------------
__device__ __forceinline__ uint32_t f2t(float f) {
  uint32_t u;
  asm("cvt.rna.tf32.f32 %0, %1;" : "=r"(u) : "f"(f));
  return u;
}
__device__ __forceinline__ uint4 cvt4(float4 v) {
  return make_uint4(f2t(v.x), f2t(v.y), f2t(v.z), f2t(v.w));
}
__device__ __forceinline__ void mma8(float* c, const uint32_t* a, const uint32_t* b) {
  asm volatile(
      "mma.sync.aligned.m16n8k8.row.col.f32.tf32.tf32.f32 "
      "{%0,%1,%2,%3}, {%4,%5,%6,%7}, {%8,%9}, {%0,%1,%2,%3};"
      : "+f"(c[0]), "+f"(c[1]), "+f"(c[2]), "+f"(c[3])
      : "r"(a[0]), "r"(a[1]), "r"(a[2]), "r"(a[3]), "r"(b[0]), "r"(b[1]));
}

// ---------------------------------------------------------------------------
// Dense GEMM 128x128 tile, K=1024, BK=32. 256 thr, warps 2(M)x4(N).
// scatter=1: write to [b,h,s,dk] layout (QKV proj, z picks W).
// ---------------------------------------------------------------------------
__global__ void __launch_bounds__(256, 2) gemm_tc_kernel(
    const float* __restrict__ A,
    const float* __restrict__ W0, const float* __restrict__ W1,
    const float* __restrict__ W2,
    const float* __restrict__ bi0, const float* __restrict__ bi1,
    const float* __restrict__ bi2,
    float* __restrict__ o0, float* __restrict__ o1, float* __restrict__ o2,
    int scatter) {
  __shared__ uint32_t As[128][36];   // [m][k]
  __shared__ uint32_t Bs[32][136];   // [k][n]
  const int z = blockIdx.z;
  const float* W    = (z == 0) ? W0  : (z == 1) ? W1  : W2;
  const float* bias = (z == 0) ? bi0 : (z == 1) ? bi1 : bi2;
  float* out        = (z == 0) ? o0  : (z == 1) ? o1  : o2;

  const int tid = threadIdx.x, lane = tid & 31, wid = tid >> 5;
  const int wm = (wid & 1) * 64, wn = (wid >> 1) * 32;
  const int m0 = blockIdx.y * 128, n0 = blockIdx.x * 128;
  const int ar = tid >> 3, ac = (tid & 7) * 4;
  const int br = tid >> 5, bc = (tid & 31) * 4;
  float acc[4][4][4] = {};

  for (int k0 = 0; k0 < Dn; k0 += 32) {
    float4 av[4], bv[4];
#pragma unroll
    for (int i = 0; i < 4; i++)
      av[i] = *(const float4*)(A + (size_t)(m0 + ar + 32 * i) * Dn + k0 + ac);
#pragma unroll
    for (int i = 0; i < 4; i++)
      bv[i] = *(const float4*)(W + (size_t)(k0 + br + 8 * i) * Dn + n0 + bc);
    __syncthreads();
#pragma unroll
    for (int i = 0; i < 4; i++) *(uint4*)&As[ar + 32 * i][ac] = cvt4(av[i]);
#pragma unroll
    for (int i = 0; i < 4; i++) *(uint4*)&Bs[br + 8 * i][bc] = cvt4(bv[i]);
    __syncthreads();
#pragma unroll
    for (int k8 = 0; k8 < 4; k8++) {
      const int kq = k8 * 8 + (lane & 3);
      uint32_t af[4][4], bf[4][2];
#pragma unroll
      for (int mt = 0; mt < 4; mt++) {
        int r = wm + mt * 16 + (lane >> 2);
        af[mt][0] = As[r][kq];     af[mt][1] = As[r + 8][kq];
        af[mt][2] = As[r][kq + 4]; af[mt][3] = As[r + 8][kq + 4];
      }
#pragma unroll
      for (int nt = 0; nt < 4; nt++) {
        int n = wn + nt * 8 + (lane >> 2);
        bf[nt][0] = Bs[kq][n]; bf[nt][1] = Bs[kq + 4][n];
      }
#pragma unroll
      for (int mt = 0; mt < 4; mt++)
#pragma unroll
        for (int nt = 0; nt < 4; nt++) mma8(acc[mt][nt], af[mt], bf[nt]);
    }
  }

  const int row = lane >> 2, colq = (lane & 3) * 2;
#pragma unroll
  for (int mt = 0; mt < 4; mt++) {
#pragma unroll
    for (int nt = 0; nt < 4; nt++) {
      int gm = m0 + wm + mt * 16 + row;
      int gn = n0 + wn + nt * 8 + colq;
      float2 bb = *(const float2*)(bias + gn);
      float2 v0 = make_float2(acc[mt][nt][0] + bb.x, acc[mt][nt][1] + bb.y);
      float2 v1 = make_float2(acc[mt][nt][2] + bb.x, acc[mt][nt][3] + bb.y);
      if (scatter) {
        int b = gm >> 11, h = gn >> 6, dk = gn & 63;
        int s0 = gm & (Sn - 1), s1 = (gm + 8) & (Sn - 1);
        *(float2*)(out + ((size_t)(b * Hn + h) * Sn + s0) * DKn + dk) = v0;
        *(float2*)(out + ((size_t)(b * Hn + h) * Sn + s1) * DKn + dk) = v1;
      } else {
        *(float2*)(out + (size_t)gm * Dn + gn) = v0;
        *(float2*)(out + (size_t)(gm + 8) * Dn + gn) = v1;
      }
    }
  }
}

// ---------------------------------------------------------------------------
// Scores+exp: attn = mask ? 0 : exp(score) (unnormalized), partial row sums.
// ---------------------------------------------------------------------------
__global__ void __launch_bounds__(256, 2) scores_tc_kernel(
    const float* __restrict__ q, const float* __restrict__ k,
    const int* __restrict__ mask, float* __restrict__ attn,
    float* __restrict__ partial) {
  __shared__ uint32_t Qs[128][36];
  __shared__ uint32_t Ks[128][36];
  __shared__ float rs[128];
  const int tid = threadIdx.x, lane = tid & 31, wid = tid >> 5;
  const int wm = (wid & 1) * 64, wn = (wid >> 1) * 32;
  const int j0 = blockIdx.x * 128, i0 = blockIdx.y * 128, bh = blockIdx.z;
  const float* qb = q + (size_t)bh * Sn * DKn;
  const float* kb = k + (size_t)bh * Sn * DKn;
  const int r = tid >> 3, c = (tid & 7) * 4;
  float acc[4][4][4] = {};
  if (tid < 128) rs[tid] = 0.0f;

  for (int kh = 0; kh < 2; kh++) {
    float4 qv[4], kv[4];
#pragma unroll
    for (int i = 0; i < 4; i++) {
      qv[i] = *(const float4*)(qb + (size_t)(i0 + r + 32 * i) * DKn + kh * 32 + c);
      kv[i] = *(const float4*)(kb + (size_t)(j0 + r + 32 * i) * DKn + kh * 32 + c);
    }
    __syncthreads();
#pragma unroll
    for (int i = 0; i < 4; i++) {
      *(uint4*)&Qs[r + 32 * i][c] = cvt4(qv[i]);
      *(uint4*)&Ks[r + 32 * i][c] = cvt4(kv[i]);
    }
    __syncthreads();
#pragma unroll
    for (int k8 = 0; k8 < 4; k8++) {
      const int kq = k8 * 8 + (lane & 3);
      uint32_t af[4][4], bf[4][2];
#pragma unroll
      for (int mt = 0; mt < 4; mt++) {
        int rr = wm + mt * 16 + (lane >> 2);
        af[mt][0] = Qs[rr][kq];     af[mt][1] = Qs[rr + 8][kq];
        af[mt][2] = Qs[rr][kq + 4]; af[mt][3] = Qs[rr + 8][kq + 4];
      }
#pragma unroll
      for (int nt = 0; nt < 4; nt++) {
        int n = wn + nt * 8 + (lane >> 2);
        bf[nt][0] = Ks[n][kq]; bf[nt][1] = Ks[n][kq + 4];
      }
#pragma unroll
      for (int mt = 0; mt < 4; mt++)
#pragma unroll
        for (int nt = 0; nt < 4; nt++) mma8(acc[mt][nt], af[mt], bf[nt]);
    }
  }

  const int b = bh >> 4;
  const int row = lane >> 2, colq = (lane & 3) * 2;
  const float scale = 0.125f;
#pragma unroll
  for (int mt = 0; mt < 4; mt++) {
    float sum0 = 0.0f, sum1 = 0.0f;
#pragma unroll
    for (int nt = 0; nt < 4; nt++) {
      int gi = i0 + wm + mt * 16 + row;
      int gj = j0 + wn + nt * 8 + colq;
      int2 mv0 = *(const int2*)(mask + ((size_t)b * Sn + gi) * Sn + gj);
      int2 mv1 = *(const int2*)(mask + ((size_t)b * Sn + gi + 8) * Sn + gj);
      float e00 = mv0.x ? 0.0f : __expf(acc[mt][nt][0] * scale);
      float e01 = mv0.y ? 0.0f : __expf(acc[mt][nt][1] * scale);
      float e10 = mv1.x ? 0.0f : __expf(acc[mt][nt][2] * scale);
      float e11 = mv1.y ? 0.0f : __expf(acc[mt][nt][3] * scale);
      sum0 += e00 + e01;
      sum1 += e10 + e11;
      *(float2*)(attn + ((size_t)bh * Sn + gi) * Sn + gj) = make_float2(e00, e01);
      *(float2*)(attn + ((size_t)bh * Sn + gi + 8) * Sn + gj) = make_float2(e10, e11);
    }
    sum0 += __shfl_xor_sync(0xffffffffu, sum0, 1);
    sum0 += __shfl_xor_sync(0xffffffffu, sum0, 2);
    sum1 += __shfl_xor_sync(0xffffffffu, sum1, 1);
    sum1 += __shfl_xor_sync(0xffffffffu, sum1, 2);
    if ((lane & 3) == 0) {
      atomicAdd(&rs[wm + mt * 16 + row], sum0);
      atomicAdd(&rs[wm + mt * 16 + row + 8], sum1);
    }
  }
  __syncthreads();
  if (tid < 128)
    partial[(size_t)blockIdx.x * RowsTot + (size_t)bh * Sn + i0 + tid] = rs[tid];
}

// ---------------------------------------------------------------------------
__global__ void __launch_bounds__(256) inv_kernel(
    const float* __restrict__ partial, float* __restrict__ inv) {
  int r = blockIdx.x * 256 + threadIdx.x;
  float s = 0.0f;
#pragma unroll
  for (int jb = 0; jb < JB; jb++) s += partial[(size_t)jb * RowsTot + r];
  inv[r] = 1.0f / s;
}

// ---------------------------------------------------------------------------
// Context + normalize. 64x64 tile, BK=64, 256 thr, warps 4(M)x2(N).
// Reads raw e, writes normalized attn in place, ctx = (e*inv)@V.
// Smaller tile -> ~3 CTAs/SM -> more MLP for the DRAM-bound stream.
// ---------------------------------------------------------------------------
__global__ void __launch_bounds__(256, 3) ctx_tc_kernel(
    float* __restrict__ attn, const float* __restrict__ v,
    const float* __restrict__ inv, float* __restrict__ ctx) {
  __shared__ uint32_t As[64][68];   // e tile  [i][j]
  __shared__ uint32_t Vs[64][72];   // v tile  [j][d]
  __shared__ float invs[64];

  const int tid = threadIdx.x, lane = tid & 31, wid = tid >> 5;
  const int wm = (wid >> 1) * 16, wn = (wid & 1) * 32;
  const int i0 = blockIdx.x * 64, bh = blockIdx.y;
  float* ab = attn + (size_t)bh * Sn * Sn;
  const float* vb = v + (size_t)bh * Sn * DKn;
  const int r = tid >> 2;                 // 0..63
  const int cq = (tid & 3) * 4;           // base float col
  float acc[4][4] = {};

  if (tid < 64) invs[tid] = inv[(size_t)bh * Sn + i0 + tid];
  __syncthreads();
  const float srow = invs[r];

  for (int k0 = 0; k0 < Sn; k0 += 64) {
    float4 av[4], vv[4];
#pragma unroll
    for (int j = 0; j < 4; j++) {
      av[j] = *(const float4*)(ab + (size_t)(i0 + r) * Sn + k0 + cq + j * 16);
      vv[j] = *(const float4*)(vb + (size_t)(k0 + r) * DKn + cq + j * 16);
    }
    // normalize + write final attn in place
#pragma unroll
    for (int j = 0; j < 4; j++) {
      av[j].x *= srow; av[j].y *= srow; av[j].z *= srow; av[j].w *= srow;
      *(float4*)(ab + (size_t)(i0 + r) * Sn + k0 + cq + j * 16) = av[j];
    }
    __syncthreads();
#pragma unroll
    for (int j = 0; j < 4; j++) {
      *(uint4*)&As[r][cq + j * 16] = cvt4(av[j]);
      *(uint4*)&Vs[r][cq + j * 16] = cvt4(vv[j]);
    }
    __syncthreads();
#pragma unroll
    for (int k8 = 0; k8 < 8; k8++) {
      const int kq = k8 * 8 + (lane & 3);
      uint32_t af[4], bf[4][2];
      {
        int rr = wm + (lane >> 2);
        af[0] = As[rr][kq];     af[1] = As[rr + 8][kq];
        af[2] = As[rr][kq + 4]; af[3] = As[rr + 8][kq + 4];
      }
#pragma unroll
      for (int nt = 0; nt < 4; nt++) {
        int n = wn + nt * 8 + (lane >> 2);
        bf[nt][0] = Vs[kq][n]; bf[nt][1] = Vs[kq + 4][n];
      }
#pragma unroll
      for (int nt = 0; nt < 4; nt++) mma8(acc[nt], af, bf[nt]);
    }
    __syncthreads();
  }

  const int b = bh >> 4, h = bh & 15;
  const int row = lane >> 2, colq = (lane & 3) * 2;
#pragma unroll
  for (int nt = 0; nt < 4; nt++) {
    int gi = i0 + wm + row;
    int gd = wn + nt * 8 + colq;
    float* p = ctx + ((size_t)(b * Sn + gi)) * Dn + h * DKn + gd;
    *(float2*)p = make_float2(acc[nt][0], acc[nt][1]);
    *(float2*)(p + (size_t)8 * Dn) = make_float2(acc[nt][2], acc[nt][3]);
  }
}

// ---------------------------------------------------------------------------
// Residual + LayerNorm
// ---------------------------------------------------------------------------
__global__ void __launch_bounds__(256) ln_kernel(
    const float* __restrict__ x, const float* __restrict__ res,
    const float* __restrict__ g, const float* __restrict__ bb,
    float* __restrict__ out) {
  __shared__ float redS[8];
  __shared__ float redQ[8];
  const int tid = threadIdx.x;
  size_t base = (size_t)blockIdx.x * Dn;
  float4 xv = *(const float4*)(x + base + tid * 4);
  float4 rv = *(const float4*)(res + base + tid * 4);
  xv.x += rv.x; xv.y += rv.y; xv.z += rv.z; xv.w += rv.w;

  float s  = xv.x + xv.y + xv.z + xv.w;
  float ss = xv.x * xv.x + xv.y * xv.y + xv.z * xv.z + xv.w * xv.w;
#pragma unroll
  for (int o = 16; o; o >>= 1) {
    s  += __shfl_xor_sync(0xffffffffu, s, o);
    ss += __shfl_xor_sync(0xffffffffu, ss, o);
  }
  if ((tid & 31) == 0) { redS[tid >> 5] = s; redQ[tid >> 5] = ss; }
  __syncthreads();
  s = redS[0]; ss = redQ[0];
#pragma unroll
  for (int i = 1; i < 8; i++) { s += redS[i]; ss += redQ[i]; }

  const float invD = 1.0f / (float)Dn;
  float mu = s * invD;
  float var = ss * invD - mu * mu;
  float rstd = rsqrtf(var + 1e-5f);

  float4 gv = *(const float4*)(g + tid * 4);
  float4 bv = *(const float4*)(bb + tid * 4);
  float4 o;
  o.x = (xv.x - mu) * rstd * gv.x + bv.x;
  o.y = (xv.y - mu) * rstd * gv.y + bv.y;
  o.z = (xv.z - mu) * rstd * gv.z + bv.z;
  o.w = (xv.w - mu) * rstd * gv.w + bv.w;
  *(float4*)(out + base + tid * 4) = o;
}

// ---------------------------------------------------------------------------
extern "C" void kernel_launch(void* const* d_in, const int* in_sizes, int n_in,
                              void* d_out, int out_size) {
  const float* Q   = (const float*)d_in[0];
  const int* mask  = (const int*)d_in[3];   // bool shipped as int32
  const float* Wq  = (const float*)d_in[4];
  const float* bq  = (const float*)d_in[5];
  const float* Wk  = (const float*)d_in[6];
  const float* bk  = (const float*)d_in[7];
  const float* Wv  = (const float*)d_in[8];
  const float* bv  = (const float*)d_in[9];
  const float* Wo  = (const float*)d_in[10];
  const float* bo  = (const float*)d_in[11];
  const float* lng = (const float*)d_in[12];
  const float* lnb = (const float*)d_in[13];

  float* out_ln   = (float*)d_out;                 // [B,S,D]
  float* out_attn = out_ln + (size_t)Mn * Dn;      // [B,H,S,S]

  static float *qp = nullptr, *kp = nullptr, *vp = nullptr, *cp = nullptr,
               *xp = nullptr, *pp = nullptr, *ip = nullptr;
  if (!qp) {
    cudaGetSymbolAddress((void**)&qp, g_q);
    cudaGetSymbolAddress((void**)&kp, g_k);
    cudaGetSymbolAddress((void**)&vp, g_v);
    cudaGetSymbolAddress((void**)&cp, g_ctx);
    cudaGetSymbolAddress((void**)&xp, g_xout);
    cudaGetSymbolAddress((void**)&pp, g_partial);
    cudaGetSymbolAddress((void**)&ip, g_inv);
  }

  // fused QKV projections (mma.sync tf32)
  gemm_tc_kernel<<<dim3(Dn / 128, Mn / 128, 3), 256>>>(
      Q, Wq, Wk, Wv, bq, bk, bv, qp, kp, vp, 1);

  scores_tc_kernel<<<dim3(Sn / 128, Sn / 128, BHn), 256>>>(
      qp, kp, mask, out_attn, pp);

  inv_kernel<<<RowsTot / 256, 256>>>(pp, ip);

  ctx_tc_kernel<<<dim3(Sn / 64, BHn), 256>>>(out_attn, vp, ip, cp);

  // output projection (mma.sync tf32)
  gemm_tc_kernel<<<dim3(Dn / 128, Mn / 128, 1), 256>>>(
      cp, Wo, Wo, Wo, bo, bo, bo, xp, xp, xp, 0);

  ln_kernel<<<Mn, 256>>>(xp, Q, lng, lnb, out_ln);
}